// round 1
// baseline (speedup 1.0000x reference)
#include <cuda_runtime.h>
#include <cstdint>

#define IMH 64
#define IMW 64
#define IMC 3
#define PADV 10
#define KH_ 32
#define KW_ 32
#define LH 53
#define LW 53
#define NP 2809            // LH*LW
#define NPP 2816           // padded to 22*128
#define KD 3072            // C*KH*KW
#define NM 8192

// ---------------- scratch (static device globals: allocation-free) ----------
__device__ __align__(16) float g_P[(size_t)NPP * KD];        // 34.6 MB patches (padded rows zero)
__device__ float g_msq[NM];
__device__ __align__(16) float g_D[(size_t)NPP * NM];        // 92.3 MB distances
__device__ unsigned long long g_best[NPP];
__device__ int g_rowsel[NP];                                  // mapping[nn[p]]
__device__ float g_acc[IMC * IMH * IMW];
__device__ unsigned int g_maxbits;

// ---------------- ordered-float bit tricks ---------------------------------
__device__ __forceinline__ unsigned int fflip(float f) {
    unsigned int u = __float_as_uint(f);
    return (u & 0x80000000u) ? ~u : (u | 0x80000000u);
}
__device__ __forceinline__ float funflip(unsigned int v) {
    return __uint_as_float((v & 0x80000000u) ? (v ^ 0x80000000u) : ~v);
}

// ---------------- compensated (float-float) arithmetic ----------------------
struct ff { float hi, lo; };
__device__ __forceinline__ ff two_sum(float a, float b) {
    float s = a + b;
    float v = s - a;
    float e = (a - (s - v)) + (b - v);
    ff r; r.hi = s; r.lo = e; return r;
}
__device__ __forceinline__ ff ff_add(ff a, ff b) {
    ff s = two_sum(a.hi, b.hi);
    float lo = s.lo + a.lo + b.lo;
    float hi = s.hi + lo;
    lo = lo - (hi - s.hi);
    ff r; r.hi = hi; r.lo = lo; return r;
}
__device__ __forceinline__ ff ff_acc_prod(ff acc, float a, float b) {
    float p = a * b;
    float e = __fmaf_rn(a, b, -p);   // exact product error
    ff pe; pe.hi = p; pe.lo = e;
    return ff_add(acc, pe);
}

// ---------------- kernel 0: init per-call state ------------------------------
__global__ void k_init() {
    int i = blockIdx.x * blockDim.x + threadIdx.x;
    if (i < NPP) g_best[i] = ~0ull;
    if (i == 0) g_maxbits = 0u;
}

// ---------------- kernel 1: build patch matrix -------------------------------
// P[p][c*1024 + kh*32 + kw] = padded_image[c][i+kh][j+kw], p = i*53 + j
__global__ void k_prep(const float* __restrict__ image) {
    const size_t total = (size_t)NPP * KD;
    for (size_t idx = (size_t)blockIdx.x * blockDim.x + threadIdx.x;
         idx < total; idx += (size_t)gridDim.x * blockDim.x) {
        int p = (int)(idx / KD);
        int f = (int)(idx % KD);
        float v = 0.0f;
        if (p < NP) {
            int i = p / LW, j = p % LW;
            int c = f >> 10;
            int r = f & 1023;
            int kh = r >> 5, kw = r & 31;
            int h = i + kh - PADV;
            int w = j + kw - PADV;
            if (h >= 0 && h < IMH && w >= 0 && w < IMW)
                v = image[(h * IMW + w) * IMC + c];
        }
        g_P[idx] = v;
    }
}

// ---------------- kernel 2: row norms of mem ---------------------------------
__global__ void k_msq(const float* __restrict__ mem) {
    __shared__ float red[256];
    int n = blockIdx.x;
    const float4* r = (const float4*)(mem + (size_t)n * KD);
    float s = 0.0f;
    for (int e = threadIdx.x; e < KD / 4; e += 256) {
        float4 v = r[e];
        s += v.x * v.x + v.y * v.y + v.z * v.z + v.w * v.w;
    }
    red[threadIdx.x] = s;
    __syncthreads();
    for (int st = 128; st; st >>= 1) {
        if (threadIdx.x < st) red[threadIdx.x] += red[threadIdx.x + st];
        __syncthreads();
    }
    if (threadIdx.x == 0) g_msq[n] = red[0];
}

// ---------------- kernel 3: fp32 GEMM + distance + fused argmin --------------
// 128x128 tile, BK=8, 256 threads, 8x8 per thread.
__global__ void __launch_bounds__(256) k_gemm(const float* __restrict__ mem) {
    __shared__ __align__(16) float As[8][128];
    __shared__ __align__(16) float Bs[8][128];
    const int t  = threadIdx.x;
    const int tx = t & 15;
    const int ty = t >> 4;
    const int row0 = blockIdx.y * 128;
    const int col0 = blockIdx.x * 128;

    float acc[8][8];
#pragma unroll
    for (int i = 0; i < 8; i++)
#pragma unroll
        for (int j = 0; j < 8; j++) acc[i][j] = 0.0f;

    const int lrow = t >> 1;
    const int lkq  = (t & 1) * 4;
    const float* Ag = g_P + (size_t)(row0 + lrow) * KD + lkq;
    const float* Bg = mem + (size_t)(col0 + lrow) * KD + lkq;

    for (int k0 = 0; k0 < KD; k0 += 8) {
        float4 av = *(const float4*)(Ag + k0);
        float4 bv = *(const float4*)(Bg + k0);
        As[lkq + 0][lrow] = av.x; As[lkq + 1][lrow] = av.y;
        As[lkq + 2][lrow] = av.z; As[lkq + 3][lrow] = av.w;
        Bs[lkq + 0][lrow] = bv.x; Bs[lkq + 1][lrow] = bv.y;
        Bs[lkq + 2][lrow] = bv.z; Bs[lkq + 3][lrow] = bv.w;
        __syncthreads();
#pragma unroll
        for (int kk = 0; kk < 8; kk++) {
            float ar[8], br[8];
            *(float4*)&ar[0] = *(const float4*)&As[kk][ty * 8];
            *(float4*)&ar[4] = *(const float4*)&As[kk][ty * 8 + 4];
            *(float4*)&br[0] = *(const float4*)&Bs[kk][tx * 8];
            *(float4*)&br[4] = *(const float4*)&Bs[kk][tx * 8 + 4];
#pragma unroll
            for (int i = 0; i < 8; i++)
#pragma unroll
                for (int j = 0; j < 8; j++)
                    acc[i][j] = __fmaf_rn(ar[i], br[j], acc[i][j]);
        }
        __syncthreads();
    }

    // epilogue: d = msq[col] - 2*score; store D; per-row packed argmin
#pragma unroll
    for (int i = 0; i < 8; i++) {
        int row = row0 + ty * 8 + i;
        float dv[8];
        unsigned long long kmin = ~0ull;
#pragma unroll
        for (int j = 0; j < 8; j++) {
            int col = col0 + tx * 8 + j;
            float d = g_msq[col] - 2.0f * acc[i][j];
            dv[j] = d;
            unsigned long long key =
                ((unsigned long long)fflip(d) << 32) | (unsigned int)col;
            kmin = min(kmin, key);
        }
        float* drow = g_D + (size_t)row * NM + col0 + tx * 8;
        *(float4*)&drow[0] = *(float4*)&dv[0];
        *(float4*)&drow[4] = *(float4*)&dv[4];
#pragma unroll
        for (int off = 8; off; off >>= 1) {
            unsigned long long o = __shfl_xor_sync(0xffffffffu, kmin, off);
            kmin = min(kmin, o);
        }
        if (tx == 0) atomicMin(&g_best[row], kmin);
    }
}

// ---------------- kernel 4: exact refinement of near-ties --------------------
__global__ void __launch_bounds__(256) k_refine(const float* __restrict__ mem,
                                                const int* __restrict__ mapping) {
    __shared__ int cand[128];
    __shared__ int cnt;
    __shared__ float rdh[256], rdl[256], rmh[256], rml[256];
    __shared__ double s_bd;
    __shared__ int s_bi;

    const int p = blockIdx.x;         // < NP
    const int t = threadIdx.x;
    if (t == 0) { cnt = 0; s_bd = 1e300; s_bi = 1 << 30; }
    __syncthreads();

    const float bestd = funflip((unsigned int)(g_best[p] >> 32));
    const float thr = bestd + 0.25f;
    const float* Dp = g_D + (size_t)p * NM;
    for (int c = t; c < NM; c += 256) {
        if (Dp[c] <= thr) {
            int k = atomicAdd(&cnt, 1);
            if (k < 128) cand[k] = c;
        }
    }
    __syncthreads();
    const int nc = min(cnt, 128);
    const float* Pr = g_P + (size_t)p * KD;

    for (int k = 0; k < nc; k++) {
        int c = cand[k];
        const float* Mr = mem + (size_t)c * KD;
        ff dot; dot.hi = 0.0f; dot.lo = 0.0f;
        ff msq; msq.hi = 0.0f; msq.lo = 0.0f;
        for (int f = t; f < KD; f += 256) {
            float a = Pr[f], b = Mr[f];
            dot = ff_acc_prod(dot, a, b);
            msq = ff_acc_prod(msq, b, b);
        }
        rdh[t] = dot.hi; rdl[t] = dot.lo;
        rmh[t] = msq.hi; rml[t] = msq.lo;
        __syncthreads();
        for (int st = 128; st; st >>= 1) {
            if (t < st) {
                ff a1; a1.hi = rdh[t]; a1.lo = rdl[t];
                ff b1; b1.hi = rdh[t + st]; b1.lo = rdl[t + st];
                ff r1 = ff_add(a1, b1);
                rdh[t] = r1.hi; rdl[t] = r1.lo;
                ff a2; a2.hi = rmh[t]; a2.lo = rml[t];
                ff b2; b2.hi = rmh[t + st]; b2.lo = rml[t + st];
                ff r2 = ff_add(a2, b2);
                rmh[t] = r2.hi; rml[t] = r2.lo;
            }
            __syncthreads();
        }
        if (t == 0) {
            double dd = ((double)rmh[0] + (double)rml[0])
                      - 2.0 * ((double)rdh[0] + (double)rdl[0]);
            if (dd < s_bd || (dd == s_bd && c < s_bi)) { s_bd = dd; s_bi = c; }
        }
        __syncthreads();
    }
    if (t == 0) g_rowsel[p] = mapping[s_bi];
}

// ---------------- kernel 5: overlap-add gather + global max ------------------
// block (y, c); threads 0..63 accumulate output column x (cropped coords).
__global__ void __launch_bounds__(128) k_gather(const float* __restrict__ mem2) {
    __shared__ float seg[53][32];
    const int y = blockIdx.x;    // 0..63
    const int c = blockIdx.y;    // 0..2
    const int t = threadIdx.x;
    float acc = 0.0f;
    const int ilo = max(0, y - 21), ihi = min(52, y + 10);
    for (int i = ilo; i <= ihi; i++) {
        int kh = y + 10 - i;
        int base = c * 1024 + kh * 32;
        for (int e = t; e < 53 * 32; e += 128) {
            int j = e >> 5, kw = e & 31;
            int row = g_rowsel[i * 53 + j];
            seg[j][kw] = mem2[(size_t)row * KD + base + kw];
        }
        __syncthreads();
        if (t < 64) {
            int x = t;
            int jlo = max(0, x - 21), jhi = min(52, x + 10);
            for (int j = jlo; j <= jhi; j++) acc += seg[j][x + 10 - j];
        }
        __syncthreads();
    }
    if (t < 64) {
        g_acc[c * (IMH * IMW) + y * IMW + t] = acc;
        atomicMax(&g_maxbits, fflip(acc));
    }
}

// ---------------- kernel 6: normalize to HWC output --------------------------
__global__ void k_final(float* __restrict__ out) {
    int tid = blockIdx.x * blockDim.x + threadIdx.x;
    if (tid < IMH * IMW * IMC) {
        float mx = funflip(g_maxbits);
        int c = tid % 3;
        int x = (tid / 3) % IMW;
        int y = tid / (IMW * 3);
        out[tid] = g_acc[c * (IMH * IMW) + y * IMW + x] / mx;
    }
}

// ---------------- launcher ---------------------------------------------------
extern "C" void kernel_launch(void* const* d_in, const int* in_sizes, int n_in,
                              void* d_out, int out_size) {
    const float* image   = (const float*)d_in[0];
    const float* mem     = (const float*)d_in[1];
    const float* mem2    = (const float*)d_in[2];
    const int*   mapping = (const int*)d_in[3];
    float* out = (float*)d_out;

    k_init<<<(NPP + 255) / 256, 256>>>();
    k_prep<<<4096, 256>>>(image);
    k_msq<<<NM, 256>>>(mem);
    dim3 ggrid(NM / 128, NPP / 128);   // 64 x 22
    k_gemm<<<ggrid, 256>>>(mem);
    k_refine<<<NP, 256>>>(mem, mapping);
    k_gather<<<dim3(IMH, IMC), 128>>>(mem2);
    k_final<<<(IMH * IMW * IMC + 255) / 256, 256>>>(out);
}

// round 3
// speedup vs baseline: 5.3092x; 5.3092x over previous
#include <cuda_runtime.h>
#include <cstdint>

#define IMH 64
#define IMW 64
#define IMC 3
#define PADV 10
#define LH 53
#define LW 53
#define NP 2809            // LH*LW
#define NPP 2816           // padded to 22*128
#define KD 3072            // C*KH*KW
#define NM 8192
#define BK 64              // K per SMEM chunk (128 bytes bf16 = one SW128 atom row)
#define NCHUNK (KD / BK)   // 48

// ---------------- scratch (static device globals: allocation-free) ----------
__device__ __align__(16) float g_P[(size_t)NPP * KD];          // fp32 patches (refine)
__device__ __align__(16) unsigned short g_Pb[(size_t)NPP * KD];// bf16 patches (MMA A)
__device__ __align__(16) unsigned short g_Mb[(size_t)NM * KD]; // bf16 mem     (MMA B)
__device__ float g_msq[NM];
__device__ __align__(16) float g_D[(size_t)NPP * NM];          // bf16-accurate distances
__device__ unsigned long long g_best[NPP];
__device__ int g_rowsel[NP];
__device__ float g_acc[IMC * IMH * IMW];
__device__ unsigned int g_maxbits;

// ---------------- small helpers ---------------------------------------------
__device__ __forceinline__ unsigned int fflip(float f) {
    unsigned int u = __float_as_uint(f);
    return (u & 0x80000000u) ? ~u : (u | 0x80000000u);
}
__device__ __forceinline__ float funflip(unsigned int v) {
    return __uint_as_float((v & 0x80000000u) ? (v ^ 0x80000000u) : ~v);
}
__device__ __forceinline__ unsigned short f2bf(float f) {
    unsigned int u = __float_as_uint(f);
    u = (u + 0x7fffu + ((u >> 16) & 1u)) >> 16;
    return (unsigned short)u;
}
__device__ __forceinline__ uint32_t smem_u32(const void* p) {
    uint32_t a;
    asm("{ .reg .u64 t; cvta.to.shared.u64 t, %1; cvt.u32.u64 %0, t; }" : "=r"(a) : "l"(p));
    return a;
}
__device__ __forceinline__ uint32_t swz128(uint32_t off) {
    return off ^ ((off >> 3) & 0x70u);
}
__device__ __forceinline__ void cpasync16(uint32_t saddr, const void* gaddr) {
    asm volatile("cp.async.cg.shared.global [%0], [%1], 16;"
                 :: "r"(saddr), "l"(gaddr) : "memory");
}
__device__ __forceinline__ void cp_commit() {
    asm volatile("cp.async.commit_group;" ::: "memory");
}
__device__ __forceinline__ void cp_wait1() {
    asm volatile("cp.async.wait_group 1;" ::: "memory");
}
__device__ __forceinline__ void cp_wait0() {
    asm volatile("cp.async.wait_group 0;" ::: "memory");
}
__device__ __forceinline__ void ldsm4(uint32_t* r, uint32_t addr) {
    asm volatile("ldmatrix.sync.aligned.m8n8.x4.shared.b16 {%0,%1,%2,%3}, [%4];"
                 : "=r"(r[0]), "=r"(r[1]), "=r"(r[2]), "=r"(r[3]) : "r"(addr));
}
__device__ __forceinline__ void mma16816(float* d, const uint32_t* a,
                                         uint32_t b0, uint32_t b1) {
    asm volatile(
        "mma.sync.aligned.m16n8k16.row.col.f32.bf16.bf16.f32 "
        "{%0,%1,%2,%3},{%4,%5,%6,%7},{%8,%9},{%0,%1,%2,%3};"
        : "+f"(d[0]), "+f"(d[1]), "+f"(d[2]), "+f"(d[3])
        : "r"(a[0]), "r"(a[1]), "r"(a[2]), "r"(a[3]), "r"(b0), "r"(b1));
}

// ---------------- compensated (float-float) arithmetic ----------------------
struct ff { float hi, lo; };
__device__ __forceinline__ ff two_sum(float a, float b) {
    float s = a + b;
    float v = s - a;
    float e = (a - (s - v)) + (b - v);
    ff r; r.hi = s; r.lo = e; return r;
}
__device__ __forceinline__ ff ff_add(ff a, ff b) {
    ff s = two_sum(a.hi, b.hi);
    float lo = s.lo + a.lo + b.lo;
    float hi = s.hi + lo;
    lo = lo - (hi - s.hi);
    ff r; r.hi = hi; r.lo = lo; return r;
}
__device__ __forceinline__ ff ff_acc_prod(ff acc, float a, float b) {
    float p = a * b;
    float e = __fmaf_rn(a, b, -p);
    ff pe; pe.hi = p; pe.lo = e;
    return ff_add(acc, pe);
}

// ---------------- kernel 0: init ---------------------------------------------
__global__ void k_init() {
    int i = blockIdx.x * blockDim.x + threadIdx.x;
    if (i < NPP) g_best[i] = ~0ull;
    if (i == 0) g_maxbits = 0u;
}

// ---------------- kernel 1: build patch matrix (fp32 + bf16) ----------------
__global__ void k_prep(const float* __restrict__ image) {
    const size_t total = (size_t)NPP * KD;
    for (size_t idx = (size_t)blockIdx.x * blockDim.x + threadIdx.x;
         idx < total; idx += (size_t)gridDim.x * blockDim.x) {
        int p = (int)(idx / KD);
        int f = (int)(idx % KD);
        float v = 0.0f;
        if (p < NP) {
            int i = p / LW, j = p % LW;
            int c = f >> 10;
            int r = f & 1023;
            int kh = r >> 5, kw = r & 31;
            int h = i + kh - PADV;
            int w = j + kw - PADV;
            if (h >= 0 && h < IMH && w >= 0 && w < IMW)
                v = image[(h * IMW + w) * IMC + c];
        }
        g_P[idx] = v;
        g_Pb[idx] = f2bf(v);
    }
}

// ---------------- kernel 1b: convert mem to bf16 -----------------------------
__global__ void k_cvt(const float* __restrict__ mem) {
    const size_t total4 = (size_t)NM * KD / 4;
    const float4* src = (const float4*)mem;
    uint2* dst = (uint2*)g_Mb;
    for (size_t i = (size_t)blockIdx.x * blockDim.x + threadIdx.x;
         i < total4; i += (size_t)gridDim.x * blockDim.x) {
        float4 v = src[i];
        uint2 o;
        o.x = (uint32_t)f2bf(v.x) | ((uint32_t)f2bf(v.y) << 16);
        o.y = (uint32_t)f2bf(v.z) | ((uint32_t)f2bf(v.w) << 16);
        dst[i] = o;
    }
}

// ---------------- kernel 2: row norms of mem ---------------------------------
__global__ void k_msq(const float* __restrict__ mem) {
    __shared__ float red[256];
    int n = blockIdx.x;
    const float4* r = (const float4*)(mem + (size_t)n * KD);
    float s = 0.0f;
    for (int e = threadIdx.x; e < KD / 4; e += 256) {
        float4 v = r[e];
        s += v.x * v.x + v.y * v.y + v.z * v.z + v.w * v.w;
    }
    red[threadIdx.x] = s;
    __syncthreads();
    for (int st = 128; st; st >>= 1) {
        if (threadIdx.x < st) red[threadIdx.x] += red[threadIdx.x + st];
        __syncthreads();
    }
    if (threadIdx.x == 0) g_msq[n] = red[0];
}

// ---------------- kernel 3: bf16 mma.sync GEMM + distance + argmin -----------
// CTA tile 128x128, BK=64, double-buffered cp.async. 8 warps = 2(m) x 4(n),
// warp tile 64x32 via m16n8k16 HMMA, fp32 accum in registers.
__global__ void __launch_bounds__(256) k_gemm_mma() {
    extern __shared__ __align__(16) char dsm[];
    uint32_t base = smem_u32(dsm);
    base = (base + 1023u) & ~1023u;
    // layout: [A0 16K][B0 16K][A1 16K][B1 16K]

    const int t = threadIdx.x;
    const int lane = t & 31;
    const int wid = t >> 5;
    const int warp_m = (wid >> 2) * 64;
    const int warp_n = (wid & 3) * 32;
    const int row0 = blockIdx.y * 128;
    const int col0 = blockIdx.x * 128;

    const uint4* gA = (const uint4*)(g_Pb + (size_t)row0 * KD); // 384 uint4 per row
    const uint4* gB = (const uint4*)(g_Mb + (size_t)col0 * KD);

    float acc[4][4][4];
#pragma unroll
    for (int i = 0; i < 4; i++)
#pragma unroll
        for (int j = 0; j < 4; j++)
#pragma unroll
            for (int q = 0; q < 4; q++) acc[i][j][q] = 0.0f;

    // ldmatrix lane-invariant address parts
    const int lrow = ((lane >> 3) & 1) * 8 + (lane & 7); // row within 16-row tile
    const int lk16 = (lane >> 4) * 8;                    // k-offset within k16 step

    // ---- chunk loader (cp.async, one commit group per chunk) ----
    auto load_chunk = [&](int c, int buf) {
        const uint32_t aB = base + (uint32_t)buf * 32768u;
        const uint32_t bB = aB + 16384u;
        const int kq = c * 8;                 // chunk offset in uint4 units
#pragma unroll
        for (int it = 0; it < 8; it++) {
            int s = t + it * 256;             // 0..2047
            if (s < 1024) {                   // A: 128 rows x 8 segs
                int r = s >> 3, sc = s & 7;
                cpasync16(aB + swz128((uint32_t)(r * 128 + sc * 16)),
                          &gA[r * 384 + kq + sc]);
            } else {                          // B: 128 rows x 8 segs
                int q = s - 1024;
                int r = q >> 3, sc = q & 7;
                cpasync16(bB + swz128((uint32_t)(r * 128 + sc * 16)),
                          &gB[r * 384 + kq + sc]);
            }
        }
        cp_commit();
    };

    load_chunk(0, 0);
    load_chunk(1, 1);

    for (int c = 0; c < NCHUNK; c++) {
        if (c + 1 < NCHUNK) cp_wait1(); else cp_wait0();
        __syncthreads();

        const int buf = c & 1;
        const uint32_t aB = base + (uint32_t)buf * 32768u;
        const uint32_t bB = aB + 16384u;
#pragma unroll
        for (int ks = 0; ks < 4; ks++) {
            const int kc2 = (ks * 16 + lk16) * 2;    // byte offset of k within row
            uint32_t bfrag[2][4];
#pragma unroll
            for (int nb = 0; nb < 2; nb++) {
                uint32_t addr = bB + swz128((uint32_t)((warp_n + nb * 16 + lrow) * 128 + kc2));
                ldsm4(bfrag[nb], addr);
            }
#pragma unroll
            for (int mi = 0; mi < 4; mi++) {
                uint32_t afrag[4];
                uint32_t addr = aB + swz128((uint32_t)((warp_m + mi * 16 + lrow) * 128 + kc2));
                ldsm4(afrag, addr);
#pragma unroll
                for (int nj = 0; nj < 4; nj++) {
                    const int nb = nj >> 1, hi = nj & 1;
                    mma16816(acc[mi][nj], afrag, bfrag[nb][hi], bfrag[nb][hi + 2]);
                }
            }
        }
        __syncthreads();
        if (c + 2 < NCHUNK) load_chunk(c + 2, buf);
    }

    // ---- epilogue: distance, D store, per-row argmin ----
    const int rql = lane >> 2;          // 0..7 row-quad
    const int cpl = (lane & 3) * 2;     // col pair base
#pragma unroll
    for (int mi = 0; mi < 4; mi++) {
        int rA = row0 + warp_m + mi * 16 + rql;      // rows rA, rA+8
        unsigned long long kmin0 = ~0ull, kmin1 = ~0ull;
#pragma unroll
        for (int nj = 0; nj < 4; nj++) {
            int cb = col0 + warp_n + nj * 8 + cpl;
            float ms0 = g_msq[cb], ms1 = g_msq[cb + 1];
            float d00 = ms0 - 2.0f * acc[mi][nj][0];
            float d01 = ms1 - 2.0f * acc[mi][nj][1];
            float d10 = ms0 - 2.0f * acc[mi][nj][2];
            float d11 = ms1 - 2.0f * acc[mi][nj][3];
            float2* p0 = (float2*)&g_D[(size_t)rA * NM + cb];
            float2* p1 = (float2*)&g_D[(size_t)(rA + 8) * NM + cb];
            *p0 = make_float2(d00, d01);
            *p1 = make_float2(d10, d11);
            unsigned long long k;
            k = ((unsigned long long)fflip(d00) << 32) | (unsigned int)cb;     kmin0 = min(kmin0, k);
            k = ((unsigned long long)fflip(d01) << 32) | (unsigned int)(cb+1); kmin0 = min(kmin0, k);
            k = ((unsigned long long)fflip(d10) << 32) | (unsigned int)cb;     kmin1 = min(kmin1, k);
            k = ((unsigned long long)fflip(d11) << 32) | (unsigned int)(cb+1); kmin1 = min(kmin1, k);
        }
#pragma unroll
        for (int off = 1; off <= 2; off <<= 1) {
            kmin0 = min(kmin0, __shfl_xor_sync(0xffffffffu, kmin0, off));
            kmin1 = min(kmin1, __shfl_xor_sync(0xffffffffu, kmin1, off));
        }
        if ((lane & 3) == 0) {
            atomicMin(&g_best[rA], kmin0);
            atomicMin(&g_best[rA + 8], kmin1);
        }
    }
}

// ---------------- kernel 4: exact refinement of near-ties --------------------
__global__ void __launch_bounds__(256) k_refine(const float* __restrict__ mem,
                                                const int* __restrict__ mapping) {
    __shared__ int cand[256];
    __shared__ int cnt;
    __shared__ float rdh[256], rdl[256], rmh[256], rml[256];
    __shared__ double s_bd;
    __shared__ int s_bi;

    const int p = blockIdx.x;
    const int t = threadIdx.x;
    if (t == 0) { cnt = 0; s_bd = 1e300; s_bi = 1 << 30; }
    __syncthreads();

    const float bestd = funflip((unsigned int)(g_best[p] >> 32));
    const float thr = bestd + 4.0f;      // covers bf16 score error (>20 sigma)
    const float* Dp = g_D + (size_t)p * NM;
    for (int c = t; c < NM; c += 256) {
        if (Dp[c] <= thr) {
            int k = atomicAdd(&cnt, 1);
            if (k < 256) cand[k] = c;
        }
    }
    __syncthreads();
    const int nc = min(cnt, 256);
    const float* Pr = g_P + (size_t)p * KD;

    for (int k = 0; k < nc; k++) {
        int c = cand[k];
        const float* Mr = mem + (size_t)c * KD;
        ff dot; dot.hi = 0.0f; dot.lo = 0.0f;
        ff msq; msq.hi = 0.0f; msq.lo = 0.0f;
        for (int f = t; f < KD; f += 256) {
            float a = Pr[f], b = Mr[f];
            dot = ff_acc_prod(dot, a, b);
            msq = ff_acc_prod(msq, b, b);
        }
        rdh[t] = dot.hi; rdl[t] = dot.lo;
        rmh[t] = msq.hi; rml[t] = msq.lo;
        __syncthreads();
        for (int st = 128; st; st >>= 1) {
            if (t < st) {
                ff a1; a1.hi = rdh[t]; a1.lo = rdl[t];
                ff b1; b1.hi = rdh[t + st]; b1.lo = rdl[t + st];
                ff r1 = ff_add(a1, b1);
                rdh[t] = r1.hi; rdl[t] = r1.lo;
                ff a2; a2.hi = rmh[t]; a2.lo = rml[t];
                ff b2; b2.hi = rmh[t + st]; b2.lo = rml[t + st];
                ff r2 = ff_add(a2, b2);
                rmh[t] = r2.hi; rml[t] = r2.lo;
            }
            __syncthreads();
        }
        if (t == 0) {
            double dd = ((double)rmh[0] + (double)rml[0])
                      - 2.0 * ((double)rdh[0] + (double)rdl[0]);
            if (dd < s_bd || (dd == s_bd && c < s_bi)) { s_bd = dd; s_bi = c; }
        }
        __syncthreads();
    }
    if (t == 0) g_rowsel[p] = mapping[s_bi];
}

// ---------------- kernel 5: overlap-add gather + global max ------------------
__global__ void __launch_bounds__(128) k_gather(const float* __restrict__ mem2) {
    __shared__ float seg[53][32];
    const int y = blockIdx.x;
    const int c = blockIdx.y;
    const int t = threadIdx.x;
    float acc = 0.0f;
    const int ilo = max(0, y - 21), ihi = min(52, y + 10);
    for (int i = ilo; i <= ihi; i++) {
        int kh = y + 10 - i;
        int base = c * 1024 + kh * 32;
        for (int e = t; e < 53 * 32; e += 128) {
            int j = e >> 5, kw = e & 31;
            int row = g_rowsel[i * 53 + j];
            seg[j][kw] = mem2[(size_t)row * KD + base + kw];
        }
        __syncthreads();
        if (t < 64) {
            int x = t;
            int jlo = max(0, x - 21), jhi = min(52, x + 10);
            for (int j = jlo; j <= jhi; j++) acc += seg[j][x + 10 - j];
        }
        __syncthreads();
    }
    if (t < 64) {
        g_acc[c * (IMH * IMW) + y * IMW + t] = acc;
        atomicMax(&g_maxbits, fflip(acc));
    }
}

// ---------------- kernel 6: normalize to HWC output --------------------------
__global__ void k_final(float* __restrict__ out) {
    int tid = blockIdx.x * blockDim.x + threadIdx.x;
    if (tid < IMH * IMW * IMC) {
        float mx = funflip(g_maxbits);
        int c = tid % 3;
        int x = (tid / 3) % IMW;
        int y = tid / (IMW * 3);
        out[tid] = g_acc[c * (IMH * IMW) + y * IMW + x] / mx;
    }
}

// ---------------- launcher ---------------------------------------------------
extern "C" void kernel_launch(void* const* d_in, const int* in_sizes, int n_in,
                              void* d_out, int out_size) {
    const float* image   = (const float*)d_in[0];
    const float* mem     = (const float*)d_in[1];
    const float* mem2    = (const float*)d_in[2];
    const int*   mapping = (const int*)d_in[3];
    float* out = (float*)d_out;

    const int dyn_smem = 65536 + 1024;
    cudaFuncSetAttribute(k_gemm_mma, cudaFuncAttributeMaxDynamicSharedMemorySize, dyn_smem);

    k_init<<<(NPP + 255) / 256, 256>>>();
    k_prep<<<2048, 256>>>(image);
    k_cvt<<<2048, 256>>>(mem);
    k_msq<<<NM, 256>>>(mem);
    dim3 ggrid(NM / 128, NPP / 128);    // 64 x 22
    k_gemm_mma<<<ggrid, 256, dyn_smem>>>();
    k_refine<<<NP, 256>>>(mem, mapping);
    k_gather<<<dim3(IMH, IMC), 128>>>(mem2);
    k_final<<<(IMH * IMW * IMC + 255) / 256, 256>>>(out);
}

// round 4
// speedup vs baseline: 5.7627x; 1.0854x over previous
#include <cuda_runtime.h>
#include <cstdint>

#define IMH 64
#define IMW 64
#define IMC 3
#define PADV 10
#define LH 53
#define LW 53
#define NP 2809            // LH*LW
#define NPP 2816           // padded to 22*128
#define KD 3072            // C*KH*KW
#define NM 8192
#define BK 64              // K per SMEM chunk (128 bytes bf16 = one SW128 atom row)
#define NCHUNK (KD / BK)   // 48
#define TM 128
#define TN 256
#define NSTAGE 4
#define CHUNK_BYTES 49152u // A 16KB + B 32KB

// ---------------- scratch (static device globals: allocation-free) ----------
__device__ __align__(16) float g_P[(size_t)NPP * KD];          // fp32 patches (refine)
__device__ __align__(16) unsigned short g_Pb[(size_t)NPP * KD];// bf16 patches (MMA A)
__device__ __align__(16) unsigned short g_Mb[(size_t)NM * KD]; // bf16 mem     (MMA B)
__device__ float g_msq[NM];
__device__ __align__(16) float g_D[(size_t)NPP * NM];          // bf16-accurate distances
__device__ unsigned long long g_best[NPP];
__device__ int g_rowsel[NP];
__device__ float g_acc[IMC * IMH * IMW];
__device__ unsigned int g_maxbits;

// ---------------- small helpers ---------------------------------------------
__device__ __forceinline__ unsigned int fflip(float f) {
    unsigned int u = __float_as_uint(f);
    return (u & 0x80000000u) ? ~u : (u | 0x80000000u);
}
__device__ __forceinline__ float funflip(unsigned int v) {
    return __uint_as_float((v & 0x80000000u) ? (v ^ 0x80000000u) : ~v);
}
__device__ __forceinline__ unsigned short f2bf(float f) {
    unsigned int u = __float_as_uint(f);
    u = (u + 0x7fffu + ((u >> 16) & 1u)) >> 16;
    return (unsigned short)u;
}
__device__ __forceinline__ uint32_t smem_u32(const void* p) {
    uint32_t a;
    asm("{ .reg .u64 t; cvta.to.shared.u64 t, %1; cvt.u32.u64 %0, t; }" : "=r"(a) : "l"(p));
    return a;
}
__device__ __forceinline__ uint32_t swz128(uint32_t off) {
    return off ^ ((off >> 3) & 0x70u);
}
__device__ __forceinline__ void cpasync16(uint32_t saddr, const void* gaddr) {
    asm volatile("cp.async.cg.shared.global [%0], [%1], 16;"
                 :: "r"(saddr), "l"(gaddr) : "memory");
}
__device__ __forceinline__ void cp_commit() {
    asm volatile("cp.async.commit_group;" ::: "memory");
}
__device__ __forceinline__ void cp_wait2() {
    asm volatile("cp.async.wait_group 2;" ::: "memory");
}
__device__ __forceinline__ void cp_wait1() {
    asm volatile("cp.async.wait_group 1;" ::: "memory");
}
__device__ __forceinline__ void cp_wait0() {
    asm volatile("cp.async.wait_group 0;" ::: "memory");
}
__device__ __forceinline__ void ldsm4(uint32_t* r, uint32_t addr) {
    asm volatile("ldmatrix.sync.aligned.m8n8.x4.shared.b16 {%0,%1,%2,%3}, [%4];"
                 : "=r"(r[0]), "=r"(r[1]), "=r"(r[2]), "=r"(r[3]) : "r"(addr));
}
__device__ __forceinline__ void mma16816(float* d, const uint32_t* a,
                                         uint32_t b0, uint32_t b1) {
    asm volatile(
        "mma.sync.aligned.m16n8k16.row.col.f32.bf16.bf16.f32 "
        "{%0,%1,%2,%3},{%4,%5,%6,%7},{%8,%9},{%0,%1,%2,%3};"
        : "+f"(d[0]), "+f"(d[1]), "+f"(d[2]), "+f"(d[3])
        : "r"(a[0]), "r"(a[1]), "r"(a[2]), "r"(a[3]), "r"(b0), "r"(b1));
}

// ---------------- compensated (float-float) arithmetic ----------------------
struct ff { float hi, lo; };
__device__ __forceinline__ ff two_sum(float a, float b) {
    float s = a + b;
    float v = s - a;
    float e = (a - (s - v)) + (b - v);
    ff r; r.hi = s; r.lo = e; return r;
}
__device__ __forceinline__ ff ff_add(ff a, ff b) {
    ff s = two_sum(a.hi, b.hi);
    float lo = s.lo + a.lo + b.lo;
    float hi = s.hi + lo;
    lo = lo - (hi - s.hi);
    ff r; r.hi = hi; r.lo = lo; return r;
}
__device__ __forceinline__ ff ff_acc_prod(ff acc, float a, float b) {
    float p = a * b;
    float e = __fmaf_rn(a, b, -p);
    ff pe; pe.hi = p; pe.lo = e;
    return ff_add(acc, pe);
}

// ---------------- kernel 0: init ---------------------------------------------
__global__ void k_init() {
    int i = blockIdx.x * blockDim.x + threadIdx.x;
    if (i < NPP) g_best[i] = ~0ull;
    if (i == 0) g_maxbits = 0u;
}

// ---------------- kernel 1: build patch matrix (fp32 + bf16) ----------------
__global__ void k_prep(const float* __restrict__ image) {
    const size_t total = (size_t)NPP * KD;
    for (size_t idx = (size_t)blockIdx.x * blockDim.x + threadIdx.x;
         idx < total; idx += (size_t)gridDim.x * blockDim.x) {
        int p = (int)(idx / KD);
        int f = (int)(idx % KD);
        float v = 0.0f;
        if (p < NP) {
            int i = p / LW, j = p % LW;
            int c = f >> 10;
            int r = f & 1023;
            int kh = r >> 5, kw = r & 31;
            int h = i + kh - PADV;
            int w = j + kw - PADV;
            if (h >= 0 && h < IMH && w >= 0 && w < IMW)
                v = image[(h * IMW + w) * IMC + c];
        }
        g_P[idx] = v;
        g_Pb[idx] = f2bf(v);
    }
}

// ---------------- kernel 1b: convert mem to bf16 + row norms (fused) ---------
__global__ void __launch_bounds__(256) k_cvtmsq(const float* __restrict__ mem) {
    __shared__ float red[256];
    const int n = blockIdx.x;
    const int t = threadIdx.x;
    const float4* src = (const float4*)(mem + (size_t)n * KD);
    uint2* dst = (uint2*)(g_Mb + (size_t)n * KD);
    float s = 0.0f;
    for (int e = t; e < KD / 4; e += 256) {
        float4 v = src[e];
        s += v.x * v.x + v.y * v.y + v.z * v.z + v.w * v.w;
        uint2 o;
        o.x = (uint32_t)f2bf(v.x) | ((uint32_t)f2bf(v.y) << 16);
        o.y = (uint32_t)f2bf(v.z) | ((uint32_t)f2bf(v.w) << 16);
        dst[e] = o;
    }
    red[t] = s;
    __syncthreads();
    for (int st = 128; st; st >>= 1) {
        if (t < st) red[t] += red[t + st];
        __syncthreads();
    }
    if (t == 0) g_msq[n] = red[0];
}

// ---------------- kernel 3: bf16 mma.sync GEMM + distance + argmin -----------
// CTA tile 128x256, BK=64, 4-stage cp.async pipeline, 512 threads = 16 warps
// in a 4(m) x 4(n) grid; warp tile 32x64 via m16n8k16, fp32 accum in regs.
__global__ void __launch_bounds__(512) k_gemm_mma() {
    extern __shared__ __align__(16) char dsm[];
    uint32_t base = smem_u32(dsm);
    base = (base + 1023u) & ~1023u;
    // per stage: [A 16K][B 32K]

    const int t = threadIdx.x;
    const int lane = t & 31;
    const int wid = t >> 5;
    const int warp_m = (wid >> 2) * 32;
    const int warp_n = (wid & 3) * 64;
    const int row0 = blockIdx.y * TM;
    const int col0 = blockIdx.x * TN;

    const uint4* gA = (const uint4*)(g_Pb + (size_t)row0 * KD); // 384 uint4 per row
    const uint4* gB = (const uint4*)(g_Mb + (size_t)col0 * KD);

    float acc[2][8][4];
#pragma unroll
    for (int i = 0; i < 2; i++)
#pragma unroll
        for (int j = 0; j < 8; j++)
#pragma unroll
            for (int q = 0; q < 4; q++) acc[i][j][q] = 0.0f;

    const int lrow = ((lane >> 3) & 1) * 8 + (lane & 7); // row within 16-row tile
    const int lk16 = (lane >> 4) * 8;                    // k-offset within k16 step

    auto load_chunk = [&](int c, int buf) {
        const uint32_t aB = base + (uint32_t)buf * CHUNK_BYTES;
        const uint32_t bB = aB + 16384u;
        const int kq = c * 8;
#pragma unroll
        for (int it = 0; it < 6; it++) {
            int s = t + it * 512;             // 0..3071
            if (s < 1024) {                   // A: 128 rows x 8 segs
                int r = s >> 3, sc = s & 7;
                cpasync16(aB + swz128((uint32_t)(r * 128 + sc * 16)),
                          &gA[r * 384 + kq + sc]);
            } else {                          // B: 256 rows x 8 segs
                int q = s - 1024;
                int r = q >> 3, sc = q & 7;
                cpasync16(bB + swz128((uint32_t)(r * 128 + sc * 16)),
                          &gB[r * 384 + kq + sc]);
            }
        }
        cp_commit();
    };

    load_chunk(0, 0);
    load_chunk(1, 1);
    load_chunk(2, 2);

    for (int c = 0; c < NCHUNK; c++) {
        if (c + 2 < NCHUNK) cp_wait2();
        else if (c + 1 < NCHUNK) cp_wait1();
        else cp_wait0();
        __syncthreads();   // group c visible to all; also proves compute(c-1) done
        if (c + 3 < NCHUNK) load_chunk(c + 3, (c + 3) & 3);

        const uint32_t aB = base + (uint32_t)(c & 3) * CHUNK_BYTES;
        const uint32_t bB = aB + 16384u;
#pragma unroll
        for (int ks = 0; ks < 4; ks++) {
            const int kc2 = (ks * 16 + lk16) * 2;    // byte offset of k within row
            uint32_t bfrag[4][4];
#pragma unroll
            for (int nb = 0; nb < 4; nb++) {
                uint32_t addr = bB + swz128((uint32_t)((warp_n + nb * 16 + lrow) * 128 + kc2));
                ldsm4(bfrag[nb], addr);
            }
#pragma unroll
            for (int mi = 0; mi < 2; mi++) {
                uint32_t afrag[4];
                uint32_t addr = aB + swz128((uint32_t)((warp_m + mi * 16 + lrow) * 128 + kc2));
                ldsm4(afrag, addr);
#pragma unroll
                for (int nj = 0; nj < 8; nj++) {
                    const int nb = nj >> 1, hi = nj & 1;
                    mma16816(acc[mi][nj], afrag, bfrag[nb][hi], bfrag[nb][hi + 2]);
                }
            }
        }
    }

    // ---- epilogue: distance, D store, per-row argmin ----
    const int rql = lane >> 2;          // 0..7 row-quad
    const int cpl = (lane & 3) * 2;     // col pair base
#pragma unroll
    for (int mi = 0; mi < 2; mi++) {
        int rA = row0 + warp_m + mi * 16 + rql;      // rows rA, rA+8
        unsigned long long kmin0 = ~0ull, kmin1 = ~0ull;
#pragma unroll
        for (int nj = 0; nj < 8; nj++) {
            int cb = col0 + warp_n + nj * 8 + cpl;
            float ms0 = __ldg(&g_msq[cb]), ms1 = __ldg(&g_msq[cb + 1]);
            float d00 = ms0 - 2.0f * acc[mi][nj][0];
            float d01 = ms1 - 2.0f * acc[mi][nj][1];
            float d10 = ms0 - 2.0f * acc[mi][nj][2];
            float d11 = ms1 - 2.0f * acc[mi][nj][3];
            *(float2*)&g_D[(size_t)rA * NM + cb]       = make_float2(d00, d01);
            *(float2*)&g_D[(size_t)(rA + 8) * NM + cb] = make_float2(d10, d11);
            unsigned long long k;
            k = ((unsigned long long)fflip(d00) << 32) | (unsigned int)cb;     kmin0 = min(kmin0, k);
            k = ((unsigned long long)fflip(d01) << 32) | (unsigned int)(cb+1); kmin0 = min(kmin0, k);
            k = ((unsigned long long)fflip(d10) << 32) | (unsigned int)cb;     kmin1 = min(kmin1, k);
            k = ((unsigned long long)fflip(d11) << 32) | (unsigned int)(cb+1); kmin1 = min(kmin1, k);
        }
#pragma unroll
        for (int off = 1; off <= 2; off <<= 1) {
            kmin0 = min(kmin0, __shfl_xor_sync(0xffffffffu, kmin0, off));
            kmin1 = min(kmin1, __shfl_xor_sync(0xffffffffu, kmin1, off));
        }
        if ((lane & 3) == 0) {
            atomicMin(&g_best[rA], kmin0);
            atomicMin(&g_best[rA + 8], kmin1);
        }
    }
}

// ---------------- kernel 4: exact refinement of near-ties --------------------
__global__ void __launch_bounds__(256) k_refine(const float* __restrict__ mem,
                                                const int* __restrict__ mapping) {
    __shared__ int cand[256];
    __shared__ int cnt;
    __shared__ float rdh[256], rdl[256], rmh[256], rml[256];
    __shared__ double s_bd;
    __shared__ int s_bi;

    const int p = blockIdx.x;
    const int t = threadIdx.x;
    if (t == 0) { cnt = 0; s_bd = 1e300; s_bi = 1 << 30; }
    __syncthreads();

    const float bestd = funflip((unsigned int)(g_best[p] >> 32));
    const float thr = bestd + 4.0f;      // covers bf16 score error (>20 sigma)
    const float* Dp = g_D + (size_t)p * NM;
    for (int c = t; c < NM; c += 256) {
        if (Dp[c] <= thr) {
            int k = atomicAdd(&cnt, 1);
            if (k < 256) cand[k] = c;
        }
    }
    __syncthreads();
    const int nc = min(cnt, 256);
    const float* Pr = g_P + (size_t)p * KD;

    for (int k = 0; k < nc; k++) {
        int c = cand[k];
        const float* Mr = mem + (size_t)c * KD;
        ff dot; dot.hi = 0.0f; dot.lo = 0.0f;
        ff msq; msq.hi = 0.0f; msq.lo = 0.0f;
        for (int f = t; f < KD; f += 256) {
            float a = Pr[f], b = Mr[f];
            dot = ff_acc_prod(dot, a, b);
            msq = ff_acc_prod(msq, b, b);
        }
        rdh[t] = dot.hi; rdl[t] = dot.lo;
        rmh[t] = msq.hi; rml[t] = msq.lo;
        __syncthreads();
        for (int st = 128; st; st >>= 1) {
            if (t < st) {
                ff a1; a1.hi = rdh[t]; a1.lo = rdl[t];
                ff b1; b1.hi = rdh[t + st]; b1.lo = rdl[t + st];
                ff r1 = ff_add(a1, b1);
                rdh[t] = r1.hi; rdl[t] = r1.lo;
                ff a2; a2.hi = rmh[t]; a2.lo = rml[t];
                ff b2; b2.hi = rmh[t + st]; b2.lo = rml[t + st];
                ff r2 = ff_add(a2, b2);
                rmh[t] = r2.hi; rml[t] = r2.lo;
            }
            __syncthreads();
        }
        if (t == 0) {
            double dd = ((double)rmh[0] + (double)rml[0])
                      - 2.0 * ((double)rdh[0] + (double)rdl[0]);
            if (dd < s_bd || (dd == s_bd && c < s_bi)) { s_bd = dd; s_bi = c; }
        }
        __syncthreads();
    }
    if (t == 0) g_rowsel[p] = mapping[s_bi];
}

// ---------------- kernel 5: overlap-add gather + global max ------------------
__global__ void __launch_bounds__(128) k_gather(const float* __restrict__ mem2) {
    __shared__ float seg[53][32];
    const int y = blockIdx.x;
    const int c = blockIdx.y;
    const int t = threadIdx.x;
    float acc = 0.0f;
    const int ilo = max(0, y - 21), ihi = min(52, y + 10);
    for (int i = ilo; i <= ihi; i++) {
        int kh = y + 10 - i;
        int base = c * 1024 + kh * 32;
        for (int e = t; e < 53 * 32; e += 128) {
            int j = e >> 5, kw = e & 31;
            int row = g_rowsel[i * 53 + j];
            seg[j][kw] = mem2[(size_t)row * KD + base + kw];
        }
        __syncthreads();
        if (t < 64) {
            int x = t;
            int jlo = max(0, x - 21), jhi = min(52, x + 10);
            for (int j = jlo; j <= jhi; j++) acc += seg[j][x + 10 - j];
        }
        __syncthreads();
    }
    if (t < 64) {
        g_acc[c * (IMH * IMW) + y * IMW + t] = acc;
        atomicMax(&g_maxbits, fflip(acc));
    }
}

// ---------------- kernel 6: normalize to HWC output --------------------------
__global__ void k_final(float* __restrict__ out) {
    int tid = blockIdx.x * blockDim.x + threadIdx.x;
    if (tid < IMH * IMW * IMC) {
        float mx = funflip(g_maxbits);
        int c = tid % 3;
        int x = (tid / 3) % IMW;
        int y = tid / (IMW * 3);
        out[tid] = g_acc[c * (IMH * IMW) + y * IMW + x] / mx;
    }
}

// ---------------- launcher ---------------------------------------------------
extern "C" void kernel_launch(void* const* d_in, const int* in_sizes, int n_in,
                              void* d_out, int out_size) {
    const float* image   = (const float*)d_in[0];
    const float* mem     = (const float*)d_in[1];
    const float* mem2    = (const float*)d_in[2];
    const int*   mapping = (const int*)d_in[3];
    float* out = (float*)d_out;

    const int dyn_smem = NSTAGE * (int)CHUNK_BYTES + 1024;   // 197632
    cudaFuncSetAttribute(k_gemm_mma, cudaFuncAttributeMaxDynamicSharedMemorySize, dyn_smem);

    k_init<<<(NPP + 255) / 256, 256>>>();
    k_prep<<<2048, 256>>>(image);
    k_cvtmsq<<<NM, 256>>>(mem);
    dim3 ggrid(NM / TN, NPP / TM);      // 32 x 22
    k_gemm_mma<<<ggrid, 512, dyn_smem>>>();
    k_refine<<<NP, 256>>>(mem, mapping);
    k_gather<<<dim3(IMH, IMC), 128>>>(mem2);
    k_final<<<(IMH * IMW * IMC + 255) / 256, 256>>>(out);
}

// round 7
// speedup vs baseline: 5.7708x; 1.0014x over previous
#include <cuda_runtime.h>
#include <cstdint>

#define IMH 64
#define IMW 64
#define IMC 3
#define PADV 10
#define LH 53
#define LW 53
#define NP 2809            // LH*LW
#define NPP 2816           // padded to 22*128
#define KD 3072            // C*KH*KW
#define NM 8192
#define BK 64              // K per SMEM chunk (128 bytes bf16 = one SW128 atom row)
#define NCHUNK (KD / BK)   // 48
#define TM 128
#define TN 256
#define NSTAGE 4
#define CHUNK_BYTES 49152u // A 16KB + B 32KB

// ---------------- scratch (static device globals: allocation-free) ----------
__device__ __align__(16) float g_P[(size_t)NPP * KD];          // fp32 patches (refine)
__device__ __align__(16) unsigned short g_Pb[(size_t)NPP * KD];// bf16 patches (MMA A)
__device__ __align__(16) unsigned short g_Mb[(size_t)NM * KD]; // bf16 mem     (MMA B)
__device__ float g_msq[NM];
__device__ __align__(16) float g_D[(size_t)NPP * NM];          // bf16-accurate distances
__device__ unsigned long long g_best[NPP];
__device__ int g_rowsel[NP];
__device__ float g_acc[IMC * IMH * IMW];
__device__ unsigned int g_maxbits;

// ---------------- small helpers ---------------------------------------------
__device__ __forceinline__ unsigned int fflip(float f) {
    unsigned int u = __float_as_uint(f);
    return (u & 0x80000000u) ? ~u : (u | 0x80000000u);
}
__device__ __forceinline__ float funflip(unsigned int v) {
    return __uint_as_float((v & 0x80000000u) ? (v ^ 0x80000000u) : ~v);
}
__device__ __forceinline__ unsigned short f2bf(float f) {
    unsigned int u = __float_as_uint(f);
    u = (u + 0x7fffu + ((u >> 16) & 1u)) >> 16;
    return (unsigned short)u;
}
__device__ __forceinline__ uint32_t smem_u32(const void* p) {
    uint32_t a;
    asm("{ .reg .u64 t; cvta.to.shared.u64 t, %1; cvt.u32.u64 %0, t; }" : "=r"(a) : "l"(p));
    return a;
}
__device__ __forceinline__ uint32_t swz128(uint32_t off) {
    return off ^ ((off >> 3) & 0x70u);
}
__device__ __forceinline__ void cpasync16(uint32_t saddr, const void* gaddr) {
    asm volatile("cp.async.cg.shared.global [%0], [%1], 16;"
                 :: "r"(saddr), "l"(gaddr) : "memory");
}
__device__ __forceinline__ void cp_commit() {
    asm volatile("cp.async.commit_group;" ::: "memory");
}
__device__ __forceinline__ void cp_wait2() {
    asm volatile("cp.async.wait_group 2;" ::: "memory");
}
__device__ __forceinline__ void cp_wait1() {
    asm volatile("cp.async.wait_group 1;" ::: "memory");
}
__device__ __forceinline__ void cp_wait0() {
    asm volatile("cp.async.wait_group 0;" ::: "memory");
}
__device__ __forceinline__ void ldsm4(uint32_t* r, uint32_t addr) {
    asm volatile("ldmatrix.sync.aligned.m8n8.x4.shared.b16 {%0,%1,%2,%3}, [%4];"
                 : "=r"(r[0]), "=r"(r[1]), "=r"(r[2]), "=r"(r[3]) : "r"(addr));
}
__device__ __forceinline__ void mma16816(float* d, const uint32_t* a,
                                         uint32_t b0, uint32_t b1) {
    asm volatile(
        "mma.sync.aligned.m16n8k16.row.col.f32.bf16.bf16.f32 "
        "{%0,%1,%2,%3},{%4,%5,%6,%7},{%8,%9},{%0,%1,%2,%3};"
        : "+f"(d[0]), "+f"(d[1]), "+f"(d[2]), "+f"(d[3])
        : "r"(a[0]), "r"(a[1]), "r"(a[2]), "r"(a[3]), "r"(b0), "r"(b1));
}

// ---------------- compensated (float-float) arithmetic ----------------------
struct ff { float hi, lo; };
__device__ __forceinline__ ff two_sum(float a, float b) {
    float s = a + b;
    float v = s - a;
    float e = (a - (s - v)) + (b - v);
    ff r; r.hi = s; r.lo = e; return r;
}
__device__ __forceinline__ ff ff_add(ff a, ff b) {
    ff s = two_sum(a.hi, b.hi);
    float lo = s.lo + a.lo + b.lo;
    float hi = s.hi + lo;
    lo = lo - (hi - s.hi);
    ff r; r.hi = hi; r.lo = lo; return r;
}
__device__ __forceinline__ ff ff_acc_prod(ff acc, float a, float b) {
    float p = a * b;
    float e = __fmaf_rn(a, b, -p);
    ff pe; pe.hi = p; pe.lo = e;
    return ff_add(acc, pe);
}

// ---------------- kernel 0: init ---------------------------------------------
__global__ void k_init() {
    int i = blockIdx.x * blockDim.x + threadIdx.x;
    if (i < NPP) g_best[i] = ~0ull;
    if (i == 0) g_maxbits = 0u;
}

// ---------------- kernel 1: build patch matrix (fp32 + bf16) ----------------
__global__ void k_prep(const float* __restrict__ image) {
    const size_t total = (size_t)NPP * KD;
    for (size_t idx = (size_t)blockIdx.x * blockDim.x + threadIdx.x;
         idx < total; idx += (size_t)gridDim.x * blockDim.x) {
        int p = (int)(idx / KD);
        int f = (int)(idx % KD);
        float v = 0.0f;
        if (p < NP) {
            int i = p / LW, j = p % LW;
            int c = f >> 10;
            int r = f & 1023;
            int kh = r >> 5, kw = r & 31;
            int h = i + kh - PADV;
            int w = j + kw - PADV;
            if (h >= 0 && h < IMH && w >= 0 && w < IMW)
                v = image[(h * IMW + w) * IMC + c];
        }
        g_P[idx] = v;
        g_Pb[idx] = f2bf(v);
    }
}

// ---------------- kernel 1b: convert mem to bf16 + row norms (fused) ---------
__global__ void __launch_bounds__(256) k_cvtmsq(const float* __restrict__ mem) {
    __shared__ float red[256];
    const int n = blockIdx.x;
    const int t = threadIdx.x;
    const float4* src = (const float4*)(mem + (size_t)n * KD);
    uint2* dst = (uint2*)(g_Mb + (size_t)n * KD);
    float s = 0.0f;
    for (int e = t; e < KD / 4; e += 256) {
        float4 v = src[e];
        s += v.x * v.x + v.y * v.y + v.z * v.z + v.w * v.w;
        uint2 o;
        o.x = (uint32_t)f2bf(v.x) | ((uint32_t)f2bf(v.y) << 16);
        o.y = (uint32_t)f2bf(v.z) | ((uint32_t)f2bf(v.w) << 16);
        dst[e] = o;
    }
    red[t] = s;
    __syncthreads();
    for (int st = 128; st; st >>= 1) {
        if (t < st) red[t] += red[t + st];
        __syncthreads();
    }
    if (t == 0) g_msq[n] = red[0];
}

// ---------------- kernel 3: bf16 mma.sync GEMM + distance + argmin -----------
// CTA tile 128x256, BK=64, 4-stage cp.async pipeline, 512 threads = 16 warps
// in a 4(m) x 4(n) grid; warp tile 32x64 via m16n8k16, fp32 accum in regs.
// B fragments double-buffered across k-steps to hide LDSM latency.
__global__ void __launch_bounds__(512) k_gemm_mma() {
    extern __shared__ __align__(16) char dsm[];
    uint32_t base = smem_u32(dsm);
    base = (base + 1023u) & ~1023u;
    // per stage: [A 16K][B 32K]

    const int t = threadIdx.x;
    const int lane = t & 31;
    const int wid = t >> 5;
    const int warp_m = (wid >> 2) * 32;
    const int warp_n = (wid & 3) * 64;
    const int row0 = blockIdx.y * TM;
    const int col0 = blockIdx.x * TN;

    const uint4* gA = (const uint4*)(g_Pb + (size_t)row0 * KD); // 384 uint4 per row
    const uint4* gB = (const uint4*)(g_Mb + (size_t)col0 * KD);

    float acc[2][8][4];
#pragma unroll
    for (int i = 0; i < 2; i++)
#pragma unroll
        for (int j = 0; j < 8; j++)
#pragma unroll
            for (int q = 0; q < 4; q++) acc[i][j][q] = 0.0f;

    const int lrow = ((lane >> 3) & 1) * 8 + (lane & 7); // row within 16-row tile
    const int lk16 = (lane >> 4) * 8;                    // k-offset within k16 step

    auto load_chunk = [&](int c, int buf) {
        const uint32_t aB = base + (uint32_t)buf * CHUNK_BYTES;
        const uint32_t bB = aB + 16384u;
        const int kq = c * 8;
#pragma unroll
        for (int it = 0; it < 6; it++) {
            int s = t + it * 512;             // 0..3071
            if (s < 1024) {                   // A: 128 rows x 8 segs
                int r = s >> 3, sc = s & 7;
                cpasync16(aB + swz128((uint32_t)(r * 128 + sc * 16)),
                          &gA[r * 384 + kq + sc]);
            } else {                          // B: 256 rows x 8 segs
                int q = s - 1024;
                int r = q >> 3, sc = q & 7;
                cpasync16(bB + swz128((uint32_t)(r * 128 + sc * 16)),
                          &gB[r * 384 + kq + sc]);
            }
        }
        cp_commit();
    };

    load_chunk(0, 0);
    load_chunk(1, 1);
    load_chunk(2, 2);

    for (int c = 0; c < NCHUNK; c++) {
        if (c + 2 < NCHUNK) cp_wait2();
        else if (c + 1 < NCHUNK) cp_wait1();
        else cp_wait0();
        __syncthreads();   // group c visible to all; also proves compute(c-1) done
        if (c + 3 < NCHUNK) load_chunk(c + 3, (c + 3) & 3);

        const uint32_t aB = base + (uint32_t)(c & 3) * CHUNK_BYTES;
        const uint32_t bB = aB + 16384u;

        uint32_t bfr[2][4][4];
        // preload B fragments for ks=0
        {
            const int kc2 = lk16 * 2;
#pragma unroll
            for (int nb = 0; nb < 4; nb++)
                ldsm4(bfr[0][nb], bB + swz128((uint32_t)((warp_n + nb * 16 + lrow) * 128 + kc2)));
        }
#pragma unroll
        for (int ks = 0; ks < 4; ks++) {
            const int cur = ks & 1, nxt = cur ^ 1;
            const int kc2 = (ks * 16 + lk16) * 2;    // byte offset of k within row
            // A fragments for this ks (both mi), issued before consuming MMAs
            uint32_t af[2][4];
#pragma unroll
            for (int mi = 0; mi < 2; mi++)
                ldsm4(af[mi], aB + swz128((uint32_t)((warp_m + mi * 16 + lrow) * 128 + kc2)));
            // prefetch B fragments for ks+1 — hides LDSM latency behind 32 MMAs
            if (ks < 3) {
                const int kn2 = ((ks + 1) * 16 + lk16) * 2;
#pragma unroll
                for (int nb = 0; nb < 4; nb++)
                    ldsm4(bfr[nxt][nb], bB + swz128((uint32_t)((warp_n + nb * 16 + lrow) * 128 + kn2)));
            }
#pragma unroll
            for (int mi = 0; mi < 2; mi++) {
#pragma unroll
                for (int nj = 0; nj < 8; nj++) {
                    const int nb = nj >> 1, hi = nj & 1;
                    mma16816(acc[mi][nj], af[mi], bfr[cur][nb][hi], bfr[cur][nb][hi + 2]);
                }
            }
        }
    }

    // ---- epilogue: distance, D store, per-row argmin ----
    const int rql = lane >> 2;          // 0..7 row-quad
    const int cpl = (lane & 3) * 2;     // col pair base
#pragma unroll
    for (int mi = 0; mi < 2; mi++) {
        int rA = row0 + warp_m + mi * 16 + rql;      // rows rA, rA+8
        unsigned long long kmin0 = ~0ull, kmin1 = ~0ull;
#pragma unroll
        for (int nj = 0; nj < 8; nj++) {
            int cb = col0 + warp_n + nj * 8 + cpl;
            float ms0 = __ldg(&g_msq[cb]), ms1 = __ldg(&g_msq[cb + 1]);
            float d00 = ms0 - 2.0f * acc[mi][nj][0];
            float d01 = ms1 - 2.0f * acc[mi][nj][1];
            float d10 = ms0 - 2.0f * acc[mi][nj][2];
            float d11 = ms1 - 2.0f * acc[mi][nj][3];
            *(float2*)&g_D[(size_t)rA * NM + cb]       = make_float2(d00, d01);
            *(float2*)&g_D[(size_t)(rA + 8) * NM + cb] = make_float2(d10, d11);
            unsigned long long k;
            k = ((unsigned long long)fflip(d00) << 32) | (unsigned int)cb;     kmin0 = min(kmin0, k);
            k = ((unsigned long long)fflip(d01) << 32) | (unsigned int)(cb+1); kmin0 = min(kmin0, k);
            k = ((unsigned long long)fflip(d10) << 32) | (unsigned int)cb;     kmin1 = min(kmin1, k);
            k = ((unsigned long long)fflip(d11) << 32) | (unsigned int)(cb+1); kmin1 = min(kmin1, k);
        }
#pragma unroll
        for (int off = 1; off <= 2; off <<= 1) {
            kmin0 = min(kmin0, __shfl_xor_sync(0xffffffffu, kmin0, off));
            kmin1 = min(kmin1, __shfl_xor_sync(0xffffffffu, kmin1, off));
        }
        if ((lane & 3) == 0) {
            atomicMin(&g_best[rA], kmin0);
            atomicMin(&g_best[rA + 8], kmin1);
        }
    }
}

// ---------------- kernel 4: exact refinement of near-ties --------------------
__global__ void __launch_bounds__(256) k_refine(const float* __restrict__ mem,
                                                const int* __restrict__ mapping) {
    __shared__ int cand[256];
    __shared__ int cnt;
    __shared__ float rdh[256], rdl[256], rmh[256], rml[256];
    __shared__ double s_bd;
    __shared__ int s_bi;

    const int p = blockIdx.x;
    const int t = threadIdx.x;
    if (t == 0) { cnt = 0; s_bd = 1e300; s_bi = 1 << 30; }
    __syncthreads();

    const float bestd = funflip((unsigned int)(g_best[p] >> 32));
    const float thr = bestd + 4.0f;      // covers bf16 score error (>20 sigma)
    const float* Dp = g_D + (size_t)p * NM;
    for (int c = t; c < NM; c += 256) {
        if (Dp[c] <= thr) {
            int k = atomicAdd(&cnt, 1);
            if (k < 256) cand[k] = c;
        }
    }
    __syncthreads();
    const int nc = min(cnt, 256);
    const float* Pr = g_P + (size_t)p * KD;

    for (int k = 0; k < nc; k++) {
        int c = cand[k];
        const float* Mr = mem + (size_t)c * KD;
        ff dot; dot.hi = 0.0f; dot.lo = 0.0f;
        ff msq; msq.hi = 0.0f; msq.lo = 0.0f;
        for (int f = t; f < KD; f += 256) {
            float a = Pr[f], b = Mr[f];
            dot = ff_acc_prod(dot, a, b);
            msq = ff_acc_prod(msq, b, b);
        }
        rdh[t] = dot.hi; rdl[t] = dot.lo;
        rmh[t] = msq.hi; rml[t] = msq.lo;
        __syncthreads();
        for (int st = 128; st; st >>= 1) {
            if (t < st) {
                ff a1; a1.hi = rdh[t]; a1.lo = rdl[t];
                ff b1; b1.hi = rdh[t + st]; b1.lo = rdl[t + st];
                ff r1 = ff_add(a1, b1);
                rdh[t] = r1.hi; rdl[t] = r1.lo;
                ff a2; a2.hi = rmh[t]; a2.lo = rml[t];
                ff b2; b2.hi = rmh[t + st]; b2.lo = rml[t + st];
                ff r2 = ff_add(a2, b2);
                rmh[t] = r2.hi; rml[t] = r2.lo;
            }
            __syncthreads();
        }
        if (t == 0) {
            double dd = ((double)rmh[0] + (double)rml[0])
                      - 2.0 * ((double)rdh[0] + (double)rdl[0]);
            if (dd < s_bd || (dd == s_bd && c < s_bi)) { s_bd = dd; s_bi = c; }
        }
        __syncthreads();
    }
    if (t == 0) g_rowsel[p] = mapping[s_bi];
}

// ---------------- kernel 5: overlap-add gather + global max ------------------
__global__ void __launch_bounds__(128) k_gather(const float* __restrict__ mem2) {
    __shared__ float seg[53][32];
    const int y = blockIdx.x;
    const int c = blockIdx.y;
    const int t = threadIdx.x;
    float acc = 0.0f;
    const int ilo = max(0, y - 21), ihi = min(52, y + 10);
    for (int i = ilo; i <= ihi; i++) {
        int kh = y + 10 - i;
        int base = c * 1024 + kh * 32;
        for (int e = t; e < 53 * 32; e += 128) {
            int j = e >> 5, kw = e & 31;
            int row = g_rowsel[i * 53 + j];
            seg[j][kw] = mem2[(size_t)row * KD + base + kw];
        }
        __syncthreads();
        if (t < 64) {
            int x = t;
            int jlo = max(0, x - 21), jhi = min(52, x + 10);
            for (int j = jlo; j <= jhi; j++) acc += seg[j][x + 10 - j];
        }
        __syncthreads();
    }
    if (t < 64) {
        g_acc[c * (IMH * IMW) + y * IMW + t] = acc;
        atomicMax(&g_maxbits, fflip(acc));
    }
}

// ---------------- kernel 6: normalize to HWC output --------------------------
__global__ void k_final(float* __restrict__ out) {
    int tid = blockIdx.x * blockDim.x + threadIdx.x;
    if (tid < IMH * IMW * IMC) {
        float mx = funflip(g_maxbits);
        int c = tid % 3;
        int x = (tid / 3) % IMW;
        int y = tid / (IMW * 3);
        out[tid] = g_acc[c * (IMH * IMW) + y * IMW + x] / mx;
    }
}

// ---------------- launcher ---------------------------------------------------
extern "C" void kernel_launch(void* const* d_in, const int* in_sizes, int n_in,
                              void* d_out, int out_size) {
    const float* image   = (const float*)d_in[0];
    const float* mem     = (const float*)d_in[1];
    const float* mem2    = (const float*)d_in[2];
    const int*   mapping = (const int*)d_in[3];
    float* out = (float*)d_out;

    const int dyn_smem = NSTAGE * (int)CHUNK_BYTES + 1024;   // 197632
    cudaFuncSetAttribute(k_gemm_mma, cudaFuncAttributeMaxDynamicSharedMemorySize, dyn_smem);

    k_init<<<(NPP + 255) / 256, 256>>>();
    k_prep<<<2048, 256>>>(image);
    k_cvtmsq<<<NM, 256>>>(mem);
    dim3 ggrid(NM / TN, NPP / TM);      // 32 x 22
    k_gemm_mma<<<ggrid, 512, dyn_smem>>>();
    k_refine<<<NP, 256>>>(mem, mapping);
    k_gather<<<dim3(IMH, IMC), 128>>>(mem2);
    k_final<<<(IMH * IMW * IMC + 255) / 256, 256>>>(out);
}